// round 7
// baseline (speedup 1.0000x reference)
#include <cuda_runtime.h>
#include <cuda_bf16.h>

#define DD 16
#define LL 6
#define KK 64
#define BLOCK 128

typedef unsigned long long u64;

// Scratch: normalized mus in [l][k][d] pair-packed layout, folded alpha
// constants c2' = -10*log2e*alpha + C1*(pi/2)^2, per-layer weights.
__device__ float4 g_mu[LL * KK * (DD / 4)];
__device__ float  g_c2p[LL * KK];
__device__ float  g_wv[LL];

#define C1_        (-7.2134752044448169f)   /* -5 * log2(e)          */
#define C2SCALE_   (-14.426950408889634f)   /* -10 * log2(e)         */
#define PI_        3.14159265358979323846f
#define HALF_PI_   1.5707963267948966f
#define LN2_TENTH  0.069314718055994531f    /* 0.1 * ln(2)           */
#define CLIP_      0.99999994f              /* fp32(1.0 - 1e-7)      */

__global__ void prep_kernel(const float* __restrict__ mus,
                            const float* __restrict__ alphas,
                            const float* __restrict__ ws) {
    int tid = threadIdx.x;
    if (tid < LL) {
        float w = ws[tid];
        g_wv[tid] = expf(-w * w);
    }
    if (tid >= LL * KK) return;
    int l = tid >> 6;
    int k = tid & 63;
    const float* m = mus + l * DD * KK + k;   // [L, D, K] layout
    float v[DD];
    float s = 0.f;
#pragma unroll
    for (int d = 0; d < DD; d++) {
        v[d] = m[d * KK];
        s += v[d] * v[d];
    }
    float inv = 1.0f / sqrtf(s);
    float* dst = reinterpret_cast<float*>(&g_mu[tid * 4]);
#pragma unroll
    for (int d = 0; d < DD; d++) dst[d] = v[d] * inv;
    g_c2p[tid] = C2SCALE_ * alphas[tid] + C1_ * (HALF_PI_ * HALF_PI_);
}

// ---------- fast scalar transcendentals ----------
__device__ __forceinline__ float fast_sqrt(float x) {
    float r; asm("sqrt.approx.f32 %0, %1;" : "=f"(r) : "f"(x)); return r;
}
__device__ __forceinline__ float fast_ex2(float x) {
    float r; asm("ex2.approx.f32 %0, %1;" : "=f"(r) : "f"(x)); return r;
}
__device__ __forceinline__ float fast_lg2(float x) {
    float r; asm("lg2.approx.f32 %0, %1;" : "=f"(r) : "f"(x)); return r;
}

// ---------- packed f32x2 ops ----------
__device__ __forceinline__ u64 fma2(u64 a, u64 b, u64 c) {
    u64 d; asm("fma.rn.f32x2 %0, %1, %2, %3;" : "=l"(d) : "l"(a), "l"(b), "l"(c)); return d;
}
__device__ __forceinline__ u64 mul2(u64 a, u64 b) {
    u64 d; asm("mul.rn.f32x2 %0, %1, %2;" : "=l"(d) : "l"(a), "l"(b)); return d;
}
__device__ __forceinline__ u64 add2(u64 a, u64 b) {
    u64 d; asm("add.rn.f32x2 %0, %1, %2;" : "=l"(d) : "l"(a), "l"(b)); return d;
}
__device__ __forceinline__ u64 pack2(float lo, float hi) {
    u64 d; asm("mov.b64 %0, {%1, %2};" : "=l"(d) : "f"(lo), "f"(hi)); return d;
}
__device__ __forceinline__ void unpack2(u64 v, float& lo, float& hi) {
    asm("mov.b64 {%0, %1}, %2;" : "=f"(lo), "=f"(hi) : "l"(v));
}

// packed dot of x (8 f32 pairs) with one mu row (8 f32 pairs in 4 ulonglong2)
__device__ __forceinline__ float dot16(const u64* xp,
                                       ulonglong2 m0, ulonglong2 m1,
                                       ulonglong2 m2, ulonglong2 m3) {
    u64 a = mul2(xp[0], m0.x);
    u64 b = mul2(xp[1], m0.y);
    a = fma2(xp[2], m1.x, a);
    b = fma2(xp[3], m1.y, b);
    a = fma2(xp[4], m2.x, a);
    b = fma2(xp[5], m2.y, b);
    a = fma2(xp[6], m3.x, a);
    b = fma2(xp[7], m3.y, b);
    u64 s = add2(a, b);
    float lo, hi;
    unpack2(s, lo, hi);
    return lo + hi;
}

__global__ __launch_bounds__(BLOCK)
void main_kernel(const float* __restrict__ xs,
                 float* __restrict__ out,
                 int n_total, int n_half) {
    __shared__ ulonglong2 s_mu[LL * KK * 4];   // 24 KB
    __shared__ float2     s_c2[LL * KK / 2];   // 1.5 KB, folded c2' pairs
    __shared__ float      s_wv[LL];

    int tid = threadIdx.x;
    {
        const ulonglong2* gm = reinterpret_cast<const ulonglong2*>(g_mu);
        for (int i = tid; i < LL * KK * 4; i += BLOCK) s_mu[i] = gm[i];
        const float2* gc = reinterpret_cast<const float2*>(g_c2p);
        for (int i = tid; i < LL * KK / 2; i += BLOCK) s_c2[i] = gc[i];
        if (tid < LL) s_wv[tid] = g_wv[tid];
    }
    __syncthreads();

    // two points per thread: nA = gid, nB = gid + n_half (both coalesced)
    int gid = blockIdx.x * BLOCK + tid;
    if (gid >= n_half) return;
    int nA = gid;
    int nB = gid + n_half;
    bool hasB = (nB < n_total);

    u64 xa[8], xb[8];
    {
        const ulonglong2* xv = reinterpret_cast<const ulonglong2*>(xs + (size_t)nA * DD);
        ulonglong2 v0 = xv[0], v1 = xv[1], v2 = xv[2], v3 = xv[3];
        xa[0] = v0.x; xa[1] = v0.y; xa[2] = v1.x; xa[3] = v1.y;
        xa[4] = v2.x; xa[5] = v2.y; xa[6] = v3.x; xa[7] = v3.y;
        const ulonglong2* xw = reinterpret_cast<const ulonglong2*>(
            xs + (size_t)(hasB ? nB : nA) * DD);
        ulonglong2 w0 = xw[0], w1 = xw[1], w2 = xw[2], w3 = xw[3];
        xb[0] = w0.x; xb[1] = w0.y; xb[2] = w1.x; xb[3] = w1.y;
        xb[4] = w2.x; xb[5] = w2.y; xb[6] = w3.x; xb[7] = w3.y;
    }

    // packed acos minimax constants (duplicated lanes)
    const u64 P7 = pack2(-0.0012624911f, -0.0012624911f);
    const u64 P6 = pack2( 0.0066700901f,  0.0066700901f);
    const u64 P5 = pack2(-0.0170881256f, -0.0170881256f);
    const u64 P4 = pack2( 0.0308918810f,  0.0308918810f);
    const u64 P3 = pack2(-0.0501743046f, -0.0501743046f);
    const u64 P2 = pack2( 0.0889789874f,  0.0889789874f);
    const u64 P1 = pack2(-0.2145988016f, -0.2145988016f);
    const u64 P0 = pack2( 1.5707963050f,  1.5707963050f);
    const float Bc = -(C1_) * PI_;   // -C1*pi, linear term of dist^2 fold

    float FA = 0.f, FB = 0.f;
#pragma unroll 1
    for (int l = 0; l < LL; l++) {
        float sumA = 0.f, sumB = 0.f;
        const ulonglong2* mbase = s_mu + l * KK * 4;
        const float2*     cbase = s_c2 + l * (KK / 2);
#pragma unroll 2
        for (int kp = 0; kp < KK / 2; kp++) {
            const ulonglong2* m0p = mbase + (2 * kp) * 4;
            const ulonglong2* m1p = m0p + 4;
            ulonglong2 ma0 = m0p[0], ma1 = m0p[1], ma2 = m0p[2], ma3 = m0p[3];
            ulonglong2 mb0 = m1p[0], mb1 = m1p[1], mb2 = m1p[2], mb3 = m1p[3];

            // 4 dots: 2 k's x 2 points, sharing the mu registers
            float dA0 = dot16(xa, ma0, ma1, ma2, ma3);
            float dA1 = dot16(xa, mb0, mb1, mb2, mb3);
            float dB0 = dot16(xb, ma0, ma1, ma2, ma3);
            float dB1 = dot16(xb, mb0, mb1, mb2, mb3);

            float aA0 = fminf(fabsf(dA0), CLIP_);
            float aA1 = fminf(fabsf(dA1), CLIP_);
            float aB0 = fminf(fabsf(dB0), CLIP_);
            float aB1 = fminf(fabsf(dB1), CLIP_);

            // packed acos polynomial across each point's k-pair
            u64 pa = pack2(aA0, aA1);
            u64 pb = pack2(aB0, aB1);
            u64 qa = fma2(P7, pa, P6);
            u64 qb = fma2(P7, pb, P6);
            qa = fma2(qa, pa, P5);  qb = fma2(qb, pb, P5);
            qa = fma2(qa, pa, P4);  qb = fma2(qb, pb, P4);
            qa = fma2(qa, pa, P3);  qb = fma2(qb, pb, P3);
            qa = fma2(qa, pa, P2);  qb = fma2(qb, pb, P2);
            qa = fma2(qa, pa, P1);  qb = fma2(qb, pb, P1);
            qa = fma2(qa, pa, P0);  qb = fma2(qb, pb, P0);
            float pA0, pA1, pB0, pB1;
            unpack2(qa, pA0, pA1);
            unpack2(qb, pB0, pB1);

            float dpA0 = fast_sqrt(1.0f - aA0) * pA0;   // acos(|dot|)
            float dpA1 = fast_sqrt(1.0f - aA1) * pA1;
            float dpB0 = fast_sqrt(1.0f - aB0) * pB0;
            float dpB1 = fast_sqrt(1.0f - aB1) * pB1;

            // branch-free: dist = pi/2 - copysign(pi/2 - dp, dot)
            // arg = C1*dist^2 + c2 = (C1*c + Bc)*c + c2'   (c2' prefolded)
            float cA0 = copysignf(HALF_PI_ - dpA0, dA0);
            float cA1 = copysignf(HALF_PI_ - dpA1, dA1);
            float cB0 = copysignf(HALF_PI_ - dpB0, dB0);
            float cB1 = copysignf(HALF_PI_ - dpB1, dB1);
            float2 c2 = cbase[kp];
            float gA0 = fmaf(fmaf(C1_, cA0, Bc), cA0, c2.x);
            float gA1 = fmaf(fmaf(C1_, cA1, Bc), cA1, c2.y);
            float gB0 = fmaf(fmaf(C1_, cB0, Bc), cB0, c2.x);
            float gB1 = fmaf(fmaf(C1_, cB1, Bc), cB1, c2.y);
            sumA += fast_ex2(gA0);
            sumA += fast_ex2(gA1);
            sumB += fast_ex2(gB0);
            sumB += fast_ex2(gB1);
        }
        float w = s_wv[l];
        float mcA = LN2_TENTH * fast_lg2(sumA);
        float mcB = LN2_TENTH * fast_lg2(sumB);
        FA = fmaf(w, fmaxf(FA, 0.f), (1.0f - w) * mcA);
        FB = fmaf(w, fmaxf(FB, 0.f), (1.0f - w) * mcB);
    }

    // smooth min(F, 0): 0.1 * log(1 + exp(-10F))
    out[nA] = 0.1f * log1pf(fast_ex2(C2SCALE_ * FA));
    if (hasB) out[nB] = 0.1f * log1pf(fast_ex2(C2SCALE_ * FB));
}

extern "C" void kernel_launch(void* const* d_in, const int* in_sizes, int n_in,
                              void* d_out, int out_size) {
    const float* xs     = (const float*)d_in[0];
    const float* mus    = (const float*)d_in[1];
    const float* alphas = (const float*)d_in[2];
    const float* ws     = (const float*)d_in[3];
    float* out = (float*)d_out;

    int n_total = in_sizes[0] / DD;
    int n_half = (n_total + 1) / 2;

    prep_kernel<<<1, LL * KK>>>(mus, alphas, ws);
    int blocks = (n_half + BLOCK - 1) / BLOCK;
    main_kernel<<<blocks, BLOCK>>>(xs, out, n_total, n_half);
}

// round 8
// speedup vs baseline: 1.3457x; 1.3457x over previous
#include <cuda_runtime.h>
#include <cuda_bf16.h>

#define DD 16
#define LL 6
#define KK 64
#define BLOCK 256
#define PTS_PER_BLOCK 128   /* 4 warp-pairs x 32 points */

typedef unsigned long long u64;

// Scratch: normalized mus in [l][k][d] pair-packed layout, folded alpha
// constants c2' = -10*log2e*alpha + C1*(pi/2)^2, per-layer weights.
__device__ float4 g_mu[LL * KK * (DD / 4)];
__device__ float  g_c2p[LL * KK];
__device__ float  g_wv[LL];

#define C1_        (-7.2134752044448169f)   /* -5 * log2(e)          */
#define C2SCALE_   (-14.426950408889634f)   /* -10 * log2(e)         */
#define PI_        3.14159265358979323846f
#define HALF_PI_   1.5707963267948966f
#define LN2_TENTH  0.069314718055994531f    /* 0.1 * ln(2)           */
#define CLIP_      0.99999994f              /* fp32(1.0 - 1e-7)      */

__global__ void prep_kernel(const float* __restrict__ mus,
                            const float* __restrict__ alphas,
                            const float* __restrict__ ws) {
    int tid = threadIdx.x;
    if (tid < LL) {
        float w = ws[tid];
        g_wv[tid] = expf(-w * w);
    }
    if (tid >= LL * KK) return;
    int l = tid >> 6;
    int k = tid & 63;
    const float* m = mus + l * DD * KK + k;   // [L, D, K] layout
    float v[DD];
    float s = 0.f;
#pragma unroll
    for (int d = 0; d < DD; d++) {
        v[d] = m[d * KK];
        s += v[d] * v[d];
    }
    float inv = 1.0f / sqrtf(s);
    float* dst = reinterpret_cast<float*>(&g_mu[tid * 4]);
#pragma unroll
    for (int d = 0; d < DD; d++) dst[d] = v[d] * inv;
    g_c2p[tid] = C2SCALE_ * alphas[tid] + C1_ * (HALF_PI_ * HALF_PI_);
}

// ---------- fast scalar transcendentals ----------
__device__ __forceinline__ float fast_sqrt(float x) {
    float r; asm("sqrt.approx.f32 %0, %1;" : "=f"(r) : "f"(x)); return r;
}
__device__ __forceinline__ float fast_ex2(float x) {
    float r; asm("ex2.approx.f32 %0, %1;" : "=f"(r) : "f"(x)); return r;
}
__device__ __forceinline__ float fast_lg2(float x) {
    float r; asm("lg2.approx.f32 %0, %1;" : "=f"(r) : "f"(x)); return r;
}

// ---------- packed f32x2 ops ----------
__device__ __forceinline__ u64 fma2(u64 a, u64 b, u64 c) {
    u64 d; asm("fma.rn.f32x2 %0, %1, %2, %3;" : "=l"(d) : "l"(a), "l"(b), "l"(c)); return d;
}
__device__ __forceinline__ u64 mul2(u64 a, u64 b) {
    u64 d; asm("mul.rn.f32x2 %0, %1, %2;" : "=l"(d) : "l"(a), "l"(b)); return d;
}
__device__ __forceinline__ u64 add2(u64 a, u64 b) {
    u64 d; asm("add.rn.f32x2 %0, %1, %2;" : "=l"(d) : "l"(a), "l"(b)); return d;
}
__device__ __forceinline__ u64 pack2(float lo, float hi) {
    u64 d; asm("mov.b64 %0, {%1, %2};" : "=l"(d) : "f"(lo), "f"(hi)); return d;
}
__device__ __forceinline__ void unpack2(u64 v, float& lo, float& hi) {
    asm("mov.b64 {%0, %1}, %2;" : "=f"(lo), "=f"(hi) : "l"(v));
}

// packed dot of x (8 f32 pairs) with one mu row (8 f32 pairs in 4 ulonglong2)
__device__ __forceinline__ float dot16(const u64* xp,
                                       ulonglong2 m0, ulonglong2 m1,
                                       ulonglong2 m2, ulonglong2 m3) {
    u64 a = mul2(xp[0], m0.x);
    u64 b = mul2(xp[1], m0.y);
    a = fma2(xp[2], m1.x, a);
    b = fma2(xp[3], m1.y, b);
    a = fma2(xp[4], m2.x, a);
    b = fma2(xp[5], m2.y, b);
    a = fma2(xp[6], m3.x, a);
    b = fma2(xp[7], m3.y, b);
    u64 s = add2(a, b);
    float lo, hi;
    unpack2(s, lo, hi);
    return lo + hi;
}

__global__ __launch_bounds__(BLOCK, 5)
void main_kernel(const float* __restrict__ xs,
                 float* __restrict__ out,
                 int n_total) {
    __shared__ ulonglong2 s_mu[LL * KK * 4];          // 24 KB
    __shared__ float2     s_c2[LL * KK / 2];          // 1.5 KB folded c2' pairs
    __shared__ float      s_part[LL][2][PTS_PER_BLOCK]; // 6 KB partial sums
    __shared__ float      s_wv[LL];

    int tid = threadIdx.x;
    {
        const ulonglong2* gm = reinterpret_cast<const ulonglong2*>(g_mu);
        for (int i = tid; i < LL * KK * 4; i += BLOCK) s_mu[i] = gm[i];
        const float2* gc = reinterpret_cast<const float2*>(g_c2p);
        for (int i = tid; i < LL * KK / 2; i += BLOCK) s_c2[i] = gc[i];
        if (tid < LL) s_wv[tid] = g_wv[tid];
    }
    __syncthreads();

    // warp-pair split-K: warps (2p, 2p+1) handle the same 32 points,
    // each doing half the k range (warp-uniform smem broadcast preserved)
    int warp = tid >> 5;
    int lane = tid & 31;
    int pair = warp >> 1;
    int half = warp & 1;
    int pidx = pair * 32 + lane;                  // 0..127 point-in-block
    int n = blockIdx.x * PTS_PER_BLOCK + pidx;
    int n_clamped = (n < n_total) ? n : (n_total - 1);  // no early return: sync below

    u64 xp[8];
    {
        const ulonglong2* xv = reinterpret_cast<const ulonglong2*>(
            xs + (size_t)n_clamped * DD);
        ulonglong2 v0 = xv[0], v1 = xv[1], v2 = xv[2], v3 = xv[3];
        xp[0] = v0.x; xp[1] = v0.y; xp[2] = v1.x; xp[3] = v1.y;
        xp[4] = v2.x; xp[5] = v2.y; xp[6] = v3.x; xp[7] = v3.y;
    }

    // packed acos minimax constants (duplicated lanes)
    const u64 P7 = pack2(-0.0012624911f, -0.0012624911f);
    const u64 P6 = pack2( 0.0066700901f,  0.0066700901f);
    const u64 P5 = pack2(-0.0170881256f, -0.0170881256f);
    const u64 P4 = pack2( 0.0308918810f,  0.0308918810f);
    const u64 P3 = pack2(-0.0501743046f, -0.0501743046f);
    const u64 P2 = pack2( 0.0889789874f,  0.0889789874f);
    const u64 P1 = pack2(-0.2145988016f, -0.2145988016f);
    const u64 P0 = pack2( 1.5707963050f,  1.5707963050f);
    const float Bc = -(C1_) * PI_;   // -C1*pi, linear term of dist^2 fold

#pragma unroll 1
    for (int l = 0; l < LL; l++) {
        float sum0 = 0.f, sum1 = 0.f;
        // this warp's half of the k range for layer l
        const ulonglong2* mbase = s_mu + l * KK * 4 + half * (32 * 4);
        const float2*     cbase = s_c2 + l * (KK / 2) + half * 16;
#pragma unroll 4
        for (int kp = 0; kp < 16; kp++) {
            const ulonglong2* m0p = mbase + (2 * kp) * 4;
            const ulonglong2* m1p = m0p + 4;
            float dot0 = dot16(xp, m0p[0], m0p[1], m0p[2], m0p[3]);
            float dot1 = dot16(xp, m1p[0], m1p[1], m1p[2], m1p[3]);

            float a0 = fminf(fabsf(dot0), CLIP_);
            float a1 = fminf(fabsf(dot1), CLIP_);

            // packed acos polynomial across the k-pair
            u64 pa = pack2(a0, a1);
            u64 p = fma2(P7, pa, P6);
            p = fma2(p, pa, P5);
            p = fma2(p, pa, P4);
            p = fma2(p, pa, P3);
            p = fma2(p, pa, P2);
            p = fma2(p, pa, P1);
            p = fma2(p, pa, P0);
            float p0, p1;
            unpack2(p, p0, p1);

            float dp0 = fast_sqrt(1.0f - a0) * p0;   // acos(|dot|)
            float dp1 = fast_sqrt(1.0f - a1) * p1;

            // branch-free: dist = pi/2 - copysign(pi/2 - dp, dot)
            // arg = (C1*c + Bc)*c + c2'   (c2' prefolded)
            float c0 = copysignf(HALF_PI_ - dp0, dot0);
            float c1 = copysignf(HALF_PI_ - dp1, dot1);
            float2 c2 = cbase[kp];
            float arg0 = fmaf(fmaf(C1_, c0, Bc), c0, c2.x);
            float arg1 = fmaf(fmaf(C1_, c1, Bc), c1, c2.y);
            sum0 += fast_ex2(arg0);
            sum1 += fast_ex2(arg1);
        }
        s_part[l][half][pidx] = sum0 + sum1;
    }
    __syncthreads();

    // even warps finish: merge halves, LSE, layer recurrence, smooth-min, store
    if (half == 0) {
        float F = 0.f;
#pragma unroll
        for (int l = 0; l < LL; l++) {
            float sum = s_part[l][0][pidx] + s_part[l][1][pidx];
            float mincost = LN2_TENTH * fast_lg2(sum);
            float w = s_wv[l];
            F = fmaf(w, fmaxf(F, 0.f), (1.0f - w) * mincost);
        }
        if (n < n_total) {
            float s = fast_ex2(C2SCALE_ * F);
            out[n] = 0.1f * log1pf(s);
        }
    }
}

extern "C" void kernel_launch(void* const* d_in, const int* in_sizes, int n_in,
                              void* d_out, int out_size) {
    const float* xs     = (const float*)d_in[0];
    const float* mus    = (const float*)d_in[1];
    const float* alphas = (const float*)d_in[2];
    const float* ws     = (const float*)d_in[3];
    float* out = (float*)d_out;

    int n_total = in_sizes[0] / DD;

    prep_kernel<<<1, LL * KK>>>(mus, alphas, ws);
    int blocks = (n_total + PTS_PER_BLOCK - 1) / PTS_PER_BLOCK;
    main_kernel<<<blocks, BLOCK>>>(xs, out, n_total);
}